// round 5
// baseline (speedup 1.0000x reference)
#include <cuda_runtime.h>
#include <cstdint>

// Problem constants (fixed by the dataset)
#define GROUPS 8
#define RANK  3
#define SCALING 2.0f                     // 6.0 / 3.0
#define EPS 1e-6f

#define NELEM (4LL * 4096 * 4096)        // 67,108,864
#define N4    16777216                   // float4 count (fits int32)
#define V_PER_ROW   1024                 // float4 per d-row (4096/4)
#define V_GROUP_SHIFT 7                  // 128 float4 per group

#define TPB 256
#define V_PER_ITER 2                     // float4 per thread per loop iter
#define NBLOCKS (148 * 8)                // persistent grid: 8 CTAs/SM
#define CHUNK (TPB * V_PER_ITER)         // 512 float4 per block-iteration

__global__ __launch_bounds__(TPB, 8)
void nora_rational_kernel(
    const float4* __restrict__ x,
    float4* __restrict__ out,
    const float* __restrict__ base_num,   // [G,6]
    const float* __restrict__ base_den,   // [G,4]
    const float* __restrict__ lA_num,     // [R,6]
    const float* __restrict__ lB_num,     // [G,R]
    const float* __restrict__ lA_den,     // [R,4]
    const float* __restrict__ lB_den)     // [G,R]
{
    __shared__ float s_num[GROUPS][6];
    __shared__ float s_den[GROUPS][4];

    const int t = threadIdx.x;

    // Fuse LoRA into coefficients (80 scalar results, first 80 threads).
    if (t < GROUPS * 6) {
        int g = t / 6, k = t % 6;
        float acc = base_num[t];
        #pragma unroll
        for (int r = 0; r < RANK; ++r)
            acc = fmaf(lB_num[g * RANK + r] * SCALING, lA_num[r * 6 + k], acc);
        s_num[g][k] = acc;
    } else if (t < GROUPS * 6 + GROUPS * 4) {
        int u = t - GROUPS * 6;
        int g = u / 4, k = u % 4;
        float acc = base_den[u];
        #pragma unroll
        for (int r = 0; r < RANK; ++r)
            acc = fmaf(lB_den[g * RANK + r] * SCALING, lA_den[r * 4 + k], acc);
        s_den[g][k] = acc + EPS;
    }
    __syncthreads();

    // Persistent grid-stride loop: each iteration handles CHUNK float4 per block,
    // fully coalesced. Grid stride = NBLOCKS * CHUNK.
    const int stride = NBLOCKS * CHUNK;

    for (int base = blockIdx.x * CHUNK + t; base < N4; base += stride) {
        float4 xv[V_PER_ITER];

        // Front-batched streaming loads (evict-first; single-touch data).
        #pragma unroll
        for (int j = 0; j < V_PER_ITER; ++j)
            xv[j] = __ldcs(&x[base + j * TPB]);

        #pragma unroll
        for (int j = 0; j < V_PER_ITER; ++j) {
            const int i  = base + j * TPB;
            const int vi = i & (V_PER_ROW - 1);
            const int g  = vi >> V_GROUP_SHIFT;

            const float a0 = s_num[g][0], a1 = s_num[g][1], a2 = s_num[g][2];
            const float a3 = s_num[g][3], a4 = s_num[g][4], a5 = s_num[g][5];
            const float b0 = s_den[g][0], b1 = s_den[g][1], b2 = s_den[g][2];
            const float b3 = s_den[g][3];

            float4 v = xv[j];
            float4 ov;
            #pragma unroll
            for (int lane = 0; lane < 4; ++lane) {
                float xx = (lane == 0) ? v.x : (lane == 1) ? v.y : (lane == 2) ? v.z : v.w;
                // P(x) = a0 + a1 x + ... + a5 x^5  (Horner)
                float p = fmaf(a5, xx, a4);
                p = fmaf(p, xx, a3);
                p = fmaf(p, xx, a2);
                p = fmaf(p, xx, a1);
                p = fmaf(p, xx, a0);
                // Q(x) = 1 + |b0 x + b1 x^2 + b2 x^3 + b3 x^4|
                float z = fmaf(b3, xx, b2);
                z = fmaf(z, xx, b1);
                z = fmaf(z, xx, b0);
                float q = 1.0f + fabsf(z * xx);
                float r = __fdividef(p, q);
                if (lane == 0) ov.x = r; else if (lane == 1) ov.y = r;
                else if (lane == 2) ov.z = r; else ov.w = r;
            }
            __stcs(&out[i], ov);
        }
    }
}

extern "C" void kernel_launch(void* const* d_in, const int* in_sizes, int n_in,
                              void* d_out, int out_size)
{
    const float4* x  = (const float4*)d_in[0];
    const float* bn  = (const float*)d_in[1];
    const float* bd  = (const float*)d_in[2];
    const float* lAn = (const float*)d_in[3];
    const float* lBn = (const float*)d_in[4];
    const float* lAd = (const float*)d_in[5];
    const float* lBd = (const float*)d_in[6];

    float4* out = (float4*)d_out;

    nora_rational_kernel<<<NBLOCKS, TPB>>>(
        x, out, bn, bd, lAn, lBn, lAd, lBd);
}

// round 6
// speedup vs baseline: 1.1236x; 1.1236x over previous
#include <cuda_runtime.h>
#include <cstdint>

// Problem constants (fixed by the dataset)
#define GROUPS 8
#define RANK  3
#define SCALING 2.0f                     // 6.0 / 3.0
#define EPS 1e-6f

#define N4    16777216                   // float4 count (fits int32)
#define V_PER_ROW   1024                 // float4 per d-row (4096/4)
#define V_GROUP_SHIFT 7                  // 128 float4 per group

#define TPB 256
#define V_PER_THREAD 3                   // float4 per thread (48B in flight)
#define CHUNK (TPB * V_PER_THREAD)       // 768 float4 per block

__global__ __launch_bounds__(TPB, 6)
void nora_rational_kernel(
    const float4* __restrict__ x,
    float4* __restrict__ out,
    const float* __restrict__ base_num,   // [G,6]
    const float* __restrict__ base_den,   // [G,4]
    const float* __restrict__ lA_num,     // [R,6]
    const float* __restrict__ lB_num,     // [G,R]
    const float* __restrict__ lA_den,     // [R,4]
    const float* __restrict__ lB_den)     // [G,R]
{
    __shared__ float s_num[GROUPS][6];
    __shared__ float s_den[GROUPS][4];

    const int t = threadIdx.x;

    // Fuse LoRA into coefficients (80 scalar results, first 80 threads).
    if (t < GROUPS * 6) {
        int g = t / 6, k = t % 6;
        float acc = base_num[t];
        #pragma unroll
        for (int r = 0; r < RANK; ++r)
            acc = fmaf(lB_num[g * RANK + r] * SCALING, lA_num[r * 6 + k], acc);
        s_num[g][k] = acc;
    } else if (t < GROUPS * 6 + GROUPS * 4) {
        int u = t - GROUPS * 6;
        int g = u / 4, k = u % 4;
        float acc = base_den[u];
        #pragma unroll
        for (int r = 0; r < RANK; ++r)
            acc = fmaf(lB_den[g * RANK + r] * SCALING, lA_den[r * 4 + k], acc);
        s_den[g][k] = acc + EPS;
    }
    __syncthreads();

    // Three coalesced float4 per thread, 32-bit indexing.
    const int base = blockIdx.x * CHUNK + t;

    float4 xv[V_PER_THREAD];

    // Front-batched streaming loads (evict-first; single-touch data).
    // Guard only matters for the final partial block.
    #pragma unroll
    for (int j = 0; j < V_PER_THREAD; ++j) {
        const int i = base + j * TPB;
        if (i < N4) xv[j] = __ldcs(&x[i]);
    }

    #pragma unroll
    for (int j = 0; j < V_PER_THREAD; ++j) {
        const int i = base + j * TPB;
        if (i >= N4) break;

        const int vi = i & (V_PER_ROW - 1);
        const int g  = vi >> V_GROUP_SHIFT;

        const float a0 = s_num[g][0], a1 = s_num[g][1], a2 = s_num[g][2];
        const float a3 = s_num[g][3], a4 = s_num[g][4], a5 = s_num[g][5];
        const float b0 = s_den[g][0], b1 = s_den[g][1], b2 = s_den[g][2];
        const float b3 = s_den[g][3];

        float4 v = xv[j];
        float4 ov;
        #pragma unroll
        for (int lane = 0; lane < 4; ++lane) {
            float xx = (lane == 0) ? v.x : (lane == 1) ? v.y : (lane == 2) ? v.z : v.w;
            // P(x) = a0 + a1 x + ... + a5 x^5  (Horner)
            float p = fmaf(a5, xx, a4);
            p = fmaf(p, xx, a3);
            p = fmaf(p, xx, a2);
            p = fmaf(p, xx, a1);
            p = fmaf(p, xx, a0);
            // Q(x) = 1 + |b0 x + b1 x^2 + b2 x^3 + b3 x^4|
            float z = fmaf(b3, xx, b2);
            z = fmaf(z, xx, b1);
            z = fmaf(z, xx, b0);
            float q = 1.0f + fabsf(z * xx);
            float r = __fdividef(p, q);
            if (lane == 0) ov.x = r; else if (lane == 1) ov.y = r;
            else if (lane == 2) ov.z = r; else ov.w = r;
        }
        __stcs(&out[i], ov);
    }
}

extern "C" void kernel_launch(void* const* d_in, const int* in_sizes, int n_in,
                              void* d_out, int out_size)
{
    const float4* x  = (const float4*)d_in[0];
    const float* bn  = (const float*)d_in[1];
    const float* bd  = (const float*)d_in[2];
    const float* lAn = (const float*)d_in[3];
    const float* lBn = (const float*)d_in[4];
    const float* lAd = (const float*)d_in[5];
    const float* lBd = (const float*)d_in[6];

    float4* out = (float4*)d_out;

    const int blocks = (N4 + CHUNK - 1) / CHUNK;   // 21846 (last block partial)

    nora_rational_kernel<<<blocks, TPB>>>(
        x, out, bn, bd, lAn, lBn, lAd, lBd);
}

// round 8
// speedup vs baseline: 1.1249x; 1.0012x over previous
#include <cuda_runtime.h>
#include <cstdint>

// Problem constants (fixed by the dataset)
#define GROUPS 8
#define RANK  3
#define SCALING 2.0f                     // 6.0 / 3.0
#define EPS 1e-6f

#define N4    16777216                   // float4 count (fits int32)
#define V_PER_ROW   1024                 // float4 per d-row (4096/4)
#define V_GROUP_SHIFT 7                  // 128 float4 per group

#define TPB 256
#define V_PER_THREAD 2                   // float4 per thread (32B in flight)
#define CHUNK (TPB * V_PER_THREAD)       // 512 float4 per block

__global__ __launch_bounds__(TPB, 8)
void nora_rational_kernel(
    const float4* __restrict__ x,
    float4* __restrict__ out,
    const float* __restrict__ base_num,   // [G,6]
    const float* __restrict__ base_den,   // [G,4]
    const float* __restrict__ lA_num,     // [R,6]
    const float* __restrict__ lB_num,     // [G,R]
    const float* __restrict__ lA_den,     // [R,4]
    const float* __restrict__ lB_den)     // [G,R]
{
    __shared__ float s_num[GROUPS][6];
    __shared__ float s_den[GROUPS][4];

    const int t = threadIdx.x;

    // Fuse LoRA into coefficients (80 scalar results, first 80 threads).
    if (t < GROUPS * 6) {
        int g = t / 6, k = t % 6;
        float acc = base_num[t];
        #pragma unroll
        for (int r = 0; r < RANK; ++r)
            acc = fmaf(lB_num[g * RANK + r] * SCALING, lA_num[r * 6 + k], acc);
        s_num[g][k] = acc;
    } else if (t < GROUPS * 6 + GROUPS * 4) {
        int u = t - GROUPS * 6;
        int g = u / 4, k = u % 4;
        float acc = base_den[u];
        #pragma unroll
        for (int r = 0; r < RANK; ++r)
            acc = fmaf(lB_den[g * RANK + r] * SCALING, lA_den[r * 4 + k], acc);
        s_den[g][k] = acc + EPS;
    }
    __syncthreads();

    // Two coalesced float4 per thread, all 32-bit indexing (N4 = 2^24).
    const int base = blockIdx.x * CHUNK + t;

    float4 xv[V_PER_THREAD];

    // Front-batched streaming loads (evict-first; single-touch data).
    #pragma unroll
    for (int j = 0; j < V_PER_THREAD; ++j)
        xv[j] = __ldcs(&x[base + j * TPB]);

    #pragma unroll
    for (int j = 0; j < V_PER_THREAD; ++j) {
        const int i  = base + j * TPB;
        const int vi = i & (V_PER_ROW - 1);
        const int g  = vi >> V_GROUP_SHIFT;

        const float a0 = s_num[g][0], a1 = s_num[g][1], a2 = s_num[g][2];
        const float a3 = s_num[g][3], a4 = s_num[g][4], a5 = s_num[g][5];
        const float b0 = s_den[g][0], b1 = s_den[g][1], b2 = s_den[g][2];
        const float b3 = s_den[g][3];

        float4 v = xv[j];
        float4 ov;
        #pragma unroll
        for (int lane = 0; lane < 4; ++lane) {
            float xx = (lane == 0) ? v.x : (lane == 1) ? v.y : (lane == 2) ? v.z : v.w;
            // P(x) = a0 + a1 x + ... + a5 x^5  (Horner)
            float p = fmaf(a5, xx, a4);
            p = fmaf(p, xx, a3);
            p = fmaf(p, xx, a2);
            p = fmaf(p, xx, a1);
            p = fmaf(p, xx, a0);
            // Q(x) = 1 + |b0 x + b1 x^2 + b2 x^3 + b3 x^4|
            float z = fmaf(b3, xx, b2);
            z = fmaf(z, xx, b1);
            z = fmaf(z, xx, b0);
            float q = 1.0f + fabsf(z * xx);
            float r = __fdividef(p, q);
            if (lane == 0) ov.x = r; else if (lane == 1) ov.y = r;
            else if (lane == 2) ov.z = r; else ov.w = r;
        }
        __stcs(&out[i], ov);
    }
}

extern "C" void kernel_launch(void* const* d_in, const int* in_sizes, int n_in,
                              void* d_out, int out_size)
{
    const float4* x  = (const float4*)d_in[0];
    const float* bn  = (const float*)d_in[1];
    const float* bd  = (const float*)d_in[2];
    const float* lAn = (const float*)d_in[3];
    const float* lBn = (const float*)d_in[4];
    const float* lAd = (const float*)d_in[5];
    const float* lBd = (const float*)d_in[6];

    float4* out = (float4*)d_out;

    const int blocks = N4 / CHUNK;   // 32768, exact

    nora_rational_kernel<<<blocks, TPB>>>(
        x, out, bn, bd, lAn, lBn, lAd, lBd);
}